// round 5
// baseline (speedup 1.0000x reference)
#include <cuda_runtime.h>
#include <cstdint>
#include <math.h>

#define NN 131072
#define EE 1048576
#define ET (EE + NN)

// ---------------- scratch (device globals: no runtime allocation) ----------
__device__ float g_bufA[(size_t)NN * 256];   // 128 MB ping
__device__ float g_bufB[(size_t)NN * 256];   // 128 MB pong
__device__ float g_as[NN * 4];
__device__ float g_ad[NN * 4];
__device__ float g_alpha[(size_t)ET * 4];    // per-edge softmax weights
__device__ int   g_rowptr[NN + 1];
__device__ int   g_cnt[NN];
__device__ int   g_csum[256];
__device__ int   g_col[ET];

// packed dual-fp32 FMA: d = a*b + d (lane-wise on 2x f32)
__device__ __forceinline__ void ffma2(uint64_t& d, uint64_t a, uint64_t b) {
    asm("fma.rn.f32x2 %0, %1, %2, %0;" : "+l"(d) : "l"(a), "l"(b));
}
__device__ __forceinline__ uint64_t bcast2(float v) {
    uint64_t r;
    asm("mov.b64 %0, {%1, %1};" : "=l"(r) : "f"(v));
    return r;
}

// ---------------- embedding lookup (+ zero cnt) ----------------
__global__ void k_embed(const int* __restrict__ x, const float* __restrict__ emb,
                        float* __restrict__ out) {
    int i = blockIdx.x * blockDim.x + threadIdx.x;
    if (i < NN) g_cnt[i] = 0;
    if (i < NN * 64) out[i] = __ldg(&emb[x[i >> 6] * 64 + (i & 63)]);
}

// ---------------- CSR build ----------------
__global__ void k_hist(const int* __restrict__ ei) {
    int e = blockIdx.x * blockDim.x + threadIdx.x;
    if (e >= ET) return;
    int dst = (e < EE) ? ei[EE + e] : (e - EE);
    atomicAdd(&g_cnt[dst], 1);
}
__global__ void k_chunk_sum() {
    __shared__ int sh[256];
    int b = blockIdx.x, t = threadIdx.x;
    sh[t] = g_cnt[b * 512 + t] + g_cnt[b * 512 + 256 + t];
    __syncthreads();
    for (int o = 128; o; o >>= 1) {
        if (t < o) sh[t] += sh[t + o];
        __syncthreads();
    }
    if (!t) g_csum[b] = sh[0];
}
// per-block: scan chunk totals up to b, scan own 512 counts, write rowptr, zero cnt
__global__ void k_rowptr2() {
    __shared__ int csum[256];
    __shared__ int ch[512];
    int b = blockIdx.x, t = threadIdx.x;
    csum[t] = g_csum[t];
    ch[t]       = g_cnt[b * 512 + t];
    ch[t + 256] = g_cnt[b * 512 + 256 + t];
    __syncthreads();
    if (!t) {
        int run = 0;
        for (int i = 0; i < b; i++) run += csum[i];
        for (int i = 0; i < 512; i++) { int v = ch[i]; ch[i] = run; run += v; }
    }
    __syncthreads();
    g_rowptr[b * 512 + t]       = ch[t];
    g_rowptr[b * 512 + 256 + t] = ch[t + 256];
    g_cnt[b * 512 + t] = 0;
    g_cnt[b * 512 + 256 + t] = 0;
    if (b == 255 && !t) g_rowptr[NN] = ET;
}
__global__ void k_scatter(const int* __restrict__ ei) {
    int e = blockIdx.x * blockDim.x + threadIdx.x;
    if (e >= ET) return;
    int src, dst;
    if (e < EE) { src = ei[e]; dst = ei[EE + e]; }
    else        { src = dst = e - EE; }
    int pos = g_rowptr[dst] + atomicAdd(&g_cnt[dst], 1);
    g_col[pos] = src;
}

// ======== fp32 GEMM with packed f32x2 FMA: C[Nr,M] = A[Nr,K] @ B[K,M] ========
template <int TN>
__global__ void k_gemm(const float* __restrict__ A, const float* __restrict__ B,
                       float* __restrict__ C, int K, int M) {
    const int NI = TN / 16;
    const int NP = NI / 2;
    __shared__ float As[16][136];
    __shared__ float Bs[16][TN];

    int tid = threadIdx.x;
    int tx = tid & 15, ty = tid >> 4;
    int row0 = blockIdx.y * 128, col0 = blockIdx.x * TN;

    uint64_t acc[8][NP];
#pragma unroll
    for (int i = 0; i < 8; i++)
#pragma unroll
        for (int j = 0; j < NP; j++) acc[i][j] = 0ull;

    int a_row = tid >> 1, a_kq = (tid & 1) * 8;
    const int B_VECS = 16 * TN / 4;

    for (int k0 = 0; k0 < K; k0 += 16) {
        float4 av0 = *(const float4*)(A + (size_t)(row0 + a_row) * K + k0 + a_kq);
        float4 av1 = *(const float4*)(A + (size_t)(row0 + a_row) * K + k0 + a_kq + 4);
        As[a_kq + 0][a_row] = av0.x; As[a_kq + 1][a_row] = av0.y;
        As[a_kq + 2][a_row] = av0.z; As[a_kq + 3][a_row] = av0.w;
        As[a_kq + 4][a_row] = av1.x; As[a_kq + 5][a_row] = av1.y;
        As[a_kq + 6][a_row] = av1.z; As[a_kq + 7][a_row] = av1.w;
#pragma unroll
        for (int it = 0; it < B_VECS / 256; it++) {
            int idx = tid + it * 256;
            int bk = idx / (TN / 4), bc = (idx % (TN / 4)) * 4;
            *(float4*)&Bs[bk][bc] = *(const float4*)(B + (size_t)(k0 + bk) * M + col0 + bc);
        }
        __syncthreads();
#pragma unroll
        for (int k = 0; k < 16; k++) {
            float4 a0 = *(const float4*)&As[k][ty * 8];
            float4 a1 = *(const float4*)&As[k][ty * 8 + 4];
            uint64_t bp[NP];
#pragma unroll
            for (int j = 0; j < NP; j++)
                bp[j] = *(const uint64_t*)&Bs[k][tx * NI + j * 2];
            float ar[8] = {a0.x, a0.y, a0.z, a0.w, a1.x, a1.y, a1.z, a1.w};
#pragma unroll
            for (int i = 0; i < 8; i++) {
                uint64_t ai = bcast2(ar[i]);
#pragma unroll
                for (int j = 0; j < NP; j++) ffma2(acc[i][j], ai, bp[j]);
            }
        }
        __syncthreads();
    }
#pragma unroll
    for (int i = 0; i < 8; i++) {
        float* cp = C + (size_t)(row0 + ty * 8 + i) * M + col0 + tx * NI;
#pragma unroll
        for (int j = 0; j < NP; j++)
            *(float2*)(cp + j * 2) = *(float2*)&acc[i][j];
    }
}

// ---------------- per-node attention logits ----------------
__global__ void k_alpha(const float* __restrict__ hfeat,
                        const float* __restrict__ a_src, const float* __restrict__ a_dst,
                        float* __restrict__ as_, float* __restrict__ ad_, int H) {
    int warp = (blockIdx.x * blockDim.x + threadIdx.x) >> 5;
    int lane = threadIdx.x & 31;
    if (warp >= NN) return;
    int F = H * 64;
    const float* hrow = hfeat + (size_t)warp * F;
    for (int h = 0; h < H; h++) {
        float v0 = hrow[h * 64 + lane], v1 = hrow[h * 64 + 32 + lane];
        float s = v0 * __ldg(&a_src[h * 64 + lane]) + v1 * __ldg(&a_src[h * 64 + 32 + lane]);
        float d = v0 * __ldg(&a_dst[h * 64 + lane]) + v1 * __ldg(&a_dst[h * 64 + 32 + lane]);
#pragma unroll
        for (int o = 16; o; o >>= 1) {
            s += __shfl_down_sync(0xffffffffu, s, o);
            d += __shfl_down_sync(0xffffffffu, d, o);
        }
        if (!lane) { as_[warp * H + h] = s; ad_[warp * H + h] = d; }
    }
}

// ---------------- edge softmax weights (two-sweep, warp per dst) ----------------
template <int H>
__global__ void k_attn(const float* __restrict__ as_, const float* __restrict__ ad_,
                       float* __restrict__ alpha) {
    int warp = (blockIdx.x * blockDim.x + threadIdx.x) >> 5;
    int lane = threadIdx.x & 31;
    if (warp >= NN) return;
    int d = warp;

    float adv[H];
    if (H == 4) {
        float4 t = __ldg(&((const float4*)ad_)[d]);
        adv[0] = t.x; adv[1] = t.y; adv[2] = t.z; adv[3] = t.w;
    } else {
        adv[0] = __ldg(&ad_[d]);
    }
    float m[H], s[H];
#pragma unroll
    for (int h = 0; h < H; h++) { m[h] = -1e30f; s[h] = 0.f; }

    int beg = g_rowptr[d], end = g_rowptr[d + 1];
    for (int i = beg + lane; i < end; i += 32) {
        int src = __ldg(&g_col[i]);
        float av[H];
        if (H == 4) {
            float4 t = __ldg(&((const float4*)as_)[src]);
            av[0] = t.x; av[1] = t.y; av[2] = t.z; av[3] = t.w;
        } else av[0] = __ldg(&as_[src]);
#pragma unroll
        for (int h = 0; h < H; h++) {
            float e = av[h] + adv[h];
            e = e > 0.f ? e : 0.2f * e;
            float nm = fmaxf(m[h], e);
            s[h] = s[h] * __expf(m[h] - nm) + __expf(e - nm);
            m[h] = nm;
        }
    }
#pragma unroll
    for (int o = 16; o; o >>= 1) {
#pragma unroll
        for (int h = 0; h < H; h++) {
            float mo = __shfl_xor_sync(0xffffffffu, m[h], o);
            float so = __shfl_xor_sync(0xffffffffu, s[h], o);
            float nm = fmaxf(m[h], mo);
            s[h] = s[h] * __expf(m[h] - nm) + so * __expf(mo - nm);
            m[h] = nm;
        }
    }
    float inv[H];
#pragma unroll
    for (int h = 0; h < H; h++) inv[h] = 1.f / (s[h] + 1e-16f);

    for (int i = beg + lane; i < end; i += 32) {
        int src = __ldg(&g_col[i]);
        float av[H];
        if (H == 4) {
            float4 t = __ldg(&((const float4*)as_)[src]);
            av[0] = t.x; av[1] = t.y; av[2] = t.z; av[3] = t.w;
        } else av[0] = __ldg(&as_[src]);
        float w[H];
#pragma unroll
        for (int h = 0; h < H; h++) {
            float e = av[h] + adv[h];
            e = e > 0.f ? e : 0.2f * e;
            w[h] = __expf(e - m[h]) * inv[h];
        }
        if (H == 4) {
            float4 o4 = make_float4(w[0], w[1], w[2], w[3]);
            ((float4*)alpha)[i] = o4;
        } else alpha[i] = w[0];
    }
}

// ---------------- gather aggregation with precomputed weights ----------------
template <int H>
__global__ void k_agg2(const float* __restrict__ hfeat,
                       const float* __restrict__ alpha,
                       const float* __restrict__ bias,
                       float* __restrict__ out) {
    const int F = H * 64;
    const int PER = F / 32;
    int warp = (blockIdx.x * blockDim.x + threadIdx.x) >> 5;
    int lane = threadIdx.x & 31;
    if (warp >= NN) return;
    int d = warp;

    float acc[PER];
#pragma unroll
    for (int p = 0; p < PER; p++) acc[p] = 0.f;

    int beg = g_rowptr[d], end = g_rowptr[d + 1];
    int i = beg;
    int s_n = 0;
    float4 a4_n = make_float4(0.f, 0.f, 0.f, 0.f);
    float a1_n = 0.f;
    if (i < end) {
        s_n = __ldg(&g_col[i]);
        if (H == 4) a4_n = __ldg(&((const float4*)alpha)[i]);
        else        a1_n = __ldg(&alpha[i]);
    }
    while (i < end) {
        int s = s_n;
        float aw[H];
        if (H == 4) { aw[0] = a4_n.x; aw[1] = a4_n.y; aw[2] = a4_n.z; aw[3] = a4_n.w; }
        else        aw[0] = a1_n;
        if (i + 1 < end) {
            s_n = __ldg(&g_col[i + 1]);
            if (H == 4) a4_n = __ldg(&((const float4*)alpha)[i + 1]);
            else        a1_n = __ldg(&alpha[i + 1]);
        }
        const float* hrow = hfeat + (size_t)s * F;
        float v[PER];
#pragma unroll
        for (int p = 0; p < PER; p++) v[p] = __ldg(&hrow[lane + p * 32]);
#pragma unroll
        for (int p = 0; p < PER; p++) acc[p] += aw[H == 4 ? (p >> 1) : 0] * v[p];
        i++;
    }

    float* orow = out + (size_t)d * F;
#pragma unroll
    for (int p = 0; p < PER; p++) {
        int cidx = lane + p * 32;
        float v = acc[p] + __ldg(&bias[cidx]);
        orow[cidx] = v > 0.f ? v : (expf(v) - 1.f);   // ELU
    }
}

// ---------------- final FC: [N,64] @ [64,5] + b ----------------
__global__ void k_fc(const float* __restrict__ in, const float* __restrict__ w,
                     const float* __restrict__ b, float* __restrict__ out) {
    int n = blockIdx.x * blockDim.x + threadIdx.x;
    if (n >= NN) return;
    const float4* hp = (const float4*)(in + (size_t)n * 64);
    float acc[5];
#pragma unroll
    for (int j = 0; j < 5; j++) acc[j] = __ldg(&b[j]);
#pragma unroll
    for (int k4 = 0; k4 < 16; k4++) {
        float4 v = hp[k4];
        float hv[4] = {v.x, v.y, v.z, v.w};
#pragma unroll
        for (int cc = 0; cc < 4; cc++) {
            int k = k4 * 4 + cc;
#pragma unroll
            for (int j = 0; j < 5; j++) acc[j] += hv[cc] * __ldg(&w[k * 5 + j]);
        }
    }
#pragma unroll
    for (int j = 0; j < 5; j++) out[(size_t)n * 5 + j] = acc[j];
}

// ---------------- launch ----------------
extern "C" void kernel_launch(void* const* d_in, const int* in_sizes, int n_in,
                              void* d_out, int out_size) {
    const int*   x   = (const int*)d_in[0];
    const int*   ei  = (const int*)d_in[1];
    const float* emb = (const float*)d_in[2];
    const float* W1  = (const float*)d_in[3];
    const float* a1s = (const float*)d_in[4];
    const float* a1d = (const float*)d_in[5];
    const float* b1  = (const float*)d_in[6];
    const float* W2  = (const float*)d_in[7];
    const float* a2s = (const float*)d_in[8];
    const float* a2d = (const float*)d_in[9];
    const float* b2  = (const float*)d_in[10];
    const float* W3  = (const float*)d_in[11];
    const float* a3s = (const float*)d_in[12];
    const float* a3d = (const float*)d_in[13];
    const float* b3  = (const float*)d_in[14];
    const float* fcw = (const float*)d_in[15];
    const float* fcb = (const float*)d_in[16];
    float* out = (float*)d_out;

    float *bufA, *bufB, *as_, *ad_, *alpha;
    cudaGetSymbolAddress((void**)&bufA, g_bufA);
    cudaGetSymbolAddress((void**)&bufB, g_bufB);
    cudaGetSymbolAddress((void**)&as_, g_as);
    cudaGetSymbolAddress((void**)&ad_, g_ad);
    cudaGetSymbolAddress((void**)&alpha, g_alpha);

    const int aggBlocks = (NN * 32) / 256;   // one warp per node

    // 0: embedding (+ cnt zero)
    k_embed<<<(NN * 64) / 256, 256>>>(x, emb, bufA);
    // 1-4: CSR build
    k_hist<<<ET / 256, 256>>>(ei);
    k_chunk_sum<<<256, 256>>>();
    k_rowptr2<<<256, 256>>>();
    k_scatter<<<ET / 256, 256>>>(ei);

    // ---- layer 1: in 64 -> H=4,C=64 concat (256) ----  (launch 5 = gemm)
    { dim3 g(2, NN / 128); k_gemm<128><<<g, 256>>>(bufA, W1, bufB, 64, 256); }
    k_alpha<<<aggBlocks, 256>>>(bufB, a1s, a1d, as_, ad_, 4);
    k_attn<4><<<aggBlocks, 256>>>(as_, ad_, alpha);
    k_agg2<4><<<aggBlocks, 256>>>(bufB, alpha, b1, bufA);

    // ---- layer 2: 256 -> H=4,C=64 concat (256) ----
    { dim3 g(2, NN / 128); k_gemm<128><<<g, 256>>>(bufA, W2, bufB, 256, 256); }
    k_alpha<<<aggBlocks, 256>>>(bufB, a2s, a2d, as_, ad_, 4);
    k_attn<4><<<aggBlocks, 256>>>(as_, ad_, alpha);
    k_agg2<4><<<aggBlocks, 256>>>(bufB, alpha, b2, bufA);

    // ---- layer 3: 256 -> H=1,C=64 ----
    { dim3 g(1, NN / 128); k_gemm<64><<<g, 256>>>(bufA, W3, bufB, 256, 64); }
    k_alpha<<<aggBlocks, 256>>>(bufB, a3s, a3d, as_, ad_, 1);
    k_attn<1><<<aggBlocks, 256>>>(as_, ad_, alpha);
    k_agg2<1><<<aggBlocks, 256>>>(bufB, alpha, b3, bufA);

    // ---- FC head -> [N,5] ----
    k_fc<<<NN / 256, 256>>>(bufA, fcw, fcb, out);
}

// round 7
// speedup vs baseline: 1.0155x; 1.0155x over previous
#include <cuda_runtime.h>
#include <cstdint>
#include <math.h>

#define NN 131072
#define EE 1048576
#define ET (EE + NN)

// ---------------- scratch (device globals: no runtime allocation) ----------
__device__ float g_bufA[(size_t)NN * 256];   // 128 MB ping
__device__ float g_bufB[(size_t)NN * 256];   // 128 MB pong
__device__ float g_as[NN * 4];
__device__ float g_ad[NN * 4];
__device__ float g_alpha[(size_t)ET * 4];    // per-edge softmax weights
__device__ int   g_rowptr[NN + 1];
__device__ int   g_cnt[NN];
__device__ int   g_csum[256];
__device__ int   g_col[ET];

// packed dual-fp32 FMA: d = a*b + d (lane-wise on 2x f32)
__device__ __forceinline__ void ffma2(uint64_t& d, uint64_t a, uint64_t b) {
    asm("fma.rn.f32x2 %0, %1, %2, %0;" : "+l"(d) : "l"(a), "l"(b));
}
__device__ __forceinline__ uint64_t bcast2(float v) {
    uint64_t r;
    asm("mov.b64 %0, {%1, %1};" : "=l"(r) : "f"(v));
    return r;
}

// ---------------- embedding lookup (+ zero cnt & alpha accumulators) -------
__global__ void k_embed(const int* __restrict__ x, const float* __restrict__ emb,
                        float* __restrict__ out) {
    int i = blockIdx.x * blockDim.x + threadIdx.x;
    if (i < NN) g_cnt[i] = 0;
    if (i < NN * 4) { g_as[i] = 0.f; g_ad[i] = 0.f; }
    if (i < NN * 64) out[i] = __ldg(&emb[x[i >> 6] * 64 + (i & 63)]);
}

// ---------------- CSR build ----------------
__global__ void k_hist(const int* __restrict__ ei) {
    int e = blockIdx.x * blockDim.x + threadIdx.x;
    if (e >= ET) return;
    int dst = (e < EE) ? ei[EE + e] : (e - EE);
    atomicAdd(&g_cnt[dst], 1);
}
__global__ void k_chunk_sum() {
    __shared__ int sh[256];
    int b = blockIdx.x, t = threadIdx.x;
    sh[t] = g_cnt[b * 512 + t] + g_cnt[b * 512 + 256 + t];
    __syncthreads();
    for (int o = 128; o; o >>= 1) {
        if (t < o) sh[t] += sh[t + o];
        __syncthreads();
    }
    if (!t) g_csum[b] = sh[0];
}
__global__ void k_rowptr2() {
    __shared__ int csum[256];
    __shared__ int ch[512];
    int b = blockIdx.x, t = threadIdx.x;
    csum[t] = g_csum[t];
    ch[t]       = g_cnt[b * 512 + t];
    ch[t + 256] = g_cnt[b * 512 + 256 + t];
    __syncthreads();
    if (!t) {
        int run = 0;
        for (int i = 0; i < b; i++) run += csum[i];
        for (int i = 0; i < 512; i++) { int v = ch[i]; ch[i] = run; run += v; }
    }
    __syncthreads();
    g_rowptr[b * 512 + t]       = ch[t];
    g_rowptr[b * 512 + 256 + t] = ch[t + 256];
    g_cnt[b * 512 + t] = 0;
    g_cnt[b * 512 + 256 + t] = 0;
    if (b == 255 && !t) g_rowptr[NN] = ET;
}
__global__ void k_scatter(const int* __restrict__ ei) {
    int e = blockIdx.x * blockDim.x + threadIdx.x;
    if (e >= ET) return;
    int src, dst;
    if (e < EE) { src = ei[e]; dst = ei[EE + e]; }
    else        { src = dst = e - EE; }
    int pos = g_rowptr[dst] + atomicAdd(&g_cnt[dst], 1);
    g_col[pos] = src;
}

// ======== double-buffered fp32 GEMM + fused attention-logit epilogue ========
// C[Nr,M] = A[Nr,K] @ B[K,M]; per CTA 128 x TN tile, 256 threads, BK=16.
// Epilogue: as_[row,H], ad_[row,H] += dot(C_row_head, a_src/a_dst) via atomics.
template <int TN, int H>
__global__ void __launch_bounds__(256) k_gemm(
        const float* __restrict__ A, const float* __restrict__ B,
        float* __restrict__ C,
        const float* __restrict__ a_src, const float* __restrict__ a_dst,
        float* __restrict__ as_, float* __restrict__ ad_,
        int K, int M) {
    const int NI = TN / 16;           // cols per thread (8 or 4)
    const int NP = NI / 2;            // f32x2 pairs
    const int BIT = TN / 64;          // B float4 loads per thread
    const int GROUP = 64 / NI;        // lanes covering one head's 64 cols
    __shared__ float As[2][16][136];
    __shared__ float Bs[2][16][TN];

    int tid = threadIdx.x;
    int tx = tid & 15, ty = tid >> 4;
    int row0 = blockIdx.y * 128, col0 = blockIdx.x * TN;

    uint64_t acc[8][NP];
#pragma unroll
    for (int i = 0; i < 8; i++)
#pragma unroll
        for (int j = 0; j < NP; j++) acc[i][j] = 0ull;

    int a_row = tid >> 1, a_kq = (tid & 1) * 8;
    int b_k = tid / (TN / 4), b_c = (tid % (TN / 4)) * 4;
    const int BKSTEP = 256 / (TN / 4);   // k rows covered per iteration

    // prologue: chunk 0 -> buffer 0
    {
        const float* Ap = A + (size_t)(row0 + a_row) * K + a_kq;
        float4 av0 = *(const float4*)Ap;
        float4 av1 = *(const float4*)(Ap + 4);
        As[0][a_kq + 0][a_row] = av0.x; As[0][a_kq + 1][a_row] = av0.y;
        As[0][a_kq + 2][a_row] = av0.z; As[0][a_kq + 3][a_row] = av0.w;
        As[0][a_kq + 4][a_row] = av1.x; As[0][a_kq + 5][a_row] = av1.y;
        As[0][a_kq + 6][a_row] = av1.z; As[0][a_kq + 7][a_row] = av1.w;
#pragma unroll
        for (int it = 0; it < BIT; it++)
            *(float4*)&Bs[0][b_k + it * BKSTEP][b_c] =
                *(const float4*)(B + (size_t)(b_k + it * BKSTEP) * M + col0 + b_c);
    }
    __syncthreads();

    int CH = K / 16;
    for (int ch = 0; ch < CH; ch++) {
        int cur = ch & 1;
        float4 nav0, nav1, nbv[BIT];
        if (ch + 1 < CH) {
            int k0 = (ch + 1) * 16;
            const float* Ap = A + (size_t)(row0 + a_row) * K + k0 + a_kq;
            nav0 = *(const float4*)Ap;
            nav1 = *(const float4*)(Ap + 4);
#pragma unroll
            for (int it = 0; it < BIT; it++)
                nbv[it] = *(const float4*)(B + (size_t)(k0 + b_k + it * BKSTEP) * M + col0 + b_c);
        }
#pragma unroll
        for (int k = 0; k < 16; k++) {
            float4 a0 = *(const float4*)&As[cur][k][ty * 8];
            float4 a1 = *(const float4*)&As[cur][k][ty * 8 + 4];
            uint64_t bp[NP];
#pragma unroll
            for (int j = 0; j < NP; j++)
                bp[j] = *(const uint64_t*)&Bs[cur][k][tx * NI + j * 2];
            float ar[8] = {a0.x, a0.y, a0.z, a0.w, a1.x, a1.y, a1.z, a1.w};
#pragma unroll
            for (int i = 0; i < 8; i++) {
                uint64_t ai = bcast2(ar[i]);
#pragma unroll
                for (int j = 0; j < NP; j++) ffma2(acc[i][j], ai, bp[j]);
            }
        }
        if (ch + 1 < CH) {
            int nb = cur ^ 1;
            As[nb][a_kq + 0][a_row] = nav0.x; As[nb][a_kq + 1][a_row] = nav0.y;
            As[nb][a_kq + 2][a_row] = nav0.z; As[nb][a_kq + 3][a_row] = nav0.w;
            As[nb][a_kq + 4][a_row] = nav1.x; As[nb][a_kq + 5][a_row] = nav1.y;
            As[nb][a_kq + 6][a_row] = nav1.z; As[nb][a_kq + 7][a_row] = nav1.w;
#pragma unroll
            for (int it = 0; it < BIT; it++)
                *(float4*)&Bs[nb][b_k + it * BKSTEP][b_c] = nbv[it];
        }
        __syncthreads();
    }

    // epilogue: store C + fused attention logits
    int head = col0 / 64 + (tx * NI) / 64;
    int cib  = (tx * NI) % 64;
    float avs[NI], avd[NI];
#pragma unroll
    for (int cc = 0; cc < NI; cc++) {
        avs[cc] = __ldg(&a_src[head * 64 + cib + cc]);
        avd[cc] = __ldg(&a_dst[head * 64 + cib + cc]);
    }
#pragma unroll
    for (int i = 0; i < 8; i++) {
        int row = row0 + ty * 8 + i;
        float* cp = C + (size_t)row * M + col0 + tx * NI;
        float s = 0.f, dv = 0.f;
#pragma unroll
        for (int j = 0; j < NP; j++) {
            float2 v = *(float2*)&acc[i][j];
            *(float2*)(cp + j * 2) = v;
            s  += v.x * avs[j * 2] + v.y * avs[j * 2 + 1];
            dv += v.x * avd[j * 2] + v.y * avd[j * 2 + 1];
        }
#pragma unroll
        for (int o = 1; o < GROUP; o <<= 1) {
            s  += __shfl_xor_sync(0xffffffffu, s, o);
            dv += __shfl_xor_sync(0xffffffffu, dv, o);
        }
        if ((tx & (GROUP - 1)) == 0) {
            atomicAdd(&as_[(size_t)row * H + head], s);
            atomicAdd(&ad_[(size_t)row * H + head], dv);
        }
    }
}

// ---------------- edge softmax weights (two-sweep, warp per dst) -----------
template <int H>
__global__ void k_attn(const float* __restrict__ as_, const float* __restrict__ ad_,
                       float* __restrict__ alpha) {
    int warp = (blockIdx.x * blockDim.x + threadIdx.x) >> 5;
    int lane = threadIdx.x & 31;
    if (warp >= NN) return;
    int d = warp;

    float adv[H];
    if (H == 4) {
        float4 t = __ldg(&((const float4*)ad_)[d]);
        adv[0] = t.x; adv[1] = t.y; adv[2] = t.z; adv[3] = t.w;
    } else {
        adv[0] = __ldg(&ad_[d]);
    }
    float m[H], s[H];
#pragma unroll
    for (int h = 0; h < H; h++) { m[h] = -1e30f; s[h] = 0.f; }

    int beg = g_rowptr[d], end = g_rowptr[d + 1];
    for (int i = beg + lane; i < end; i += 32) {
        int src = __ldg(&g_col[i]);
        float av[H];
        if (H == 4) {
            float4 t = __ldg(&((const float4*)as_)[src]);
            av[0] = t.x; av[1] = t.y; av[2] = t.z; av[3] = t.w;
        } else av[0] = __ldg(&as_[src]);
#pragma unroll
        for (int h = 0; h < H; h++) {
            float e = av[h] + adv[h];
            e = e > 0.f ? e : 0.2f * e;
            float nm = fmaxf(m[h], e);
            s[h] = s[h] * __expf(m[h] - nm) + __expf(e - nm);
            m[h] = nm;
        }
    }
#pragma unroll
    for (int o = 16; o; o >>= 1) {
#pragma unroll
        for (int h = 0; h < H; h++) {
            float mo = __shfl_xor_sync(0xffffffffu, m[h], o);
            float so = __shfl_xor_sync(0xffffffffu, s[h], o);
            float nm = fmaxf(m[h], mo);
            s[h] = s[h] * __expf(m[h] - nm) + so * __expf(mo - nm);
            m[h] = nm;
        }
    }
    float inv[H];
#pragma unroll
    for (int h = 0; h < H; h++) inv[h] = 1.f / (s[h] + 1e-16f);

    for (int i = beg + lane; i < end; i += 32) {
        int src = __ldg(&g_col[i]);
        float av[H];
        if (H == 4) {
            float4 t = __ldg(&((const float4*)as_)[src]);
            av[0] = t.x; av[1] = t.y; av[2] = t.z; av[3] = t.w;
        } else av[0] = __ldg(&as_[src]);
        float w[H];
#pragma unroll
        for (int h = 0; h < H; h++) {
            float e = av[h] + adv[h];
            e = e > 0.f ? e : 0.2f * e;
            w[h] = __expf(e - m[h]) * inv[h];
        }
        if (H == 4) {
            ((float4*)alpha)[i] = make_float4(w[0], w[1], w[2], w[3]);
        } else alpha[i] = w[0];
    }
}

// ---------------- gather aggregation (+ zero alpha accumulators) -----------
template <int H>
__global__ void k_agg2(const float* __restrict__ hfeat,
                       const float* __restrict__ alpha,
                       const float* __restrict__ bias,
                       float* __restrict__ out) {
    const int F = H * 64;
    const int PER = F / 32;
    int warp = (blockIdx.x * blockDim.x + threadIdx.x) >> 5;
    int lane = threadIdx.x & 31;
    if (warp >= NN) return;
    int d = warp;

    float acc[PER];
#pragma unroll
    for (int p = 0; p < PER; p++) acc[p] = 0.f;

    int beg = g_rowptr[d], end = g_rowptr[d + 1];
    int i = beg;
    int s_n = 0;
    float4 a4_n = make_float4(0.f, 0.f, 0.f, 0.f);
    float a1_n = 0.f;
    if (i < end) {
        s_n = __ldg(&g_col[i]);
        if (H == 4) a4_n = __ldg(&((const float4*)alpha)[i]);
        else        a1_n = __ldg(&alpha[i]);
    }
    while (i < end) {
        int s = s_n;
        float aw[H];
        if (H == 4) { aw[0] = a4_n.x; aw[1] = a4_n.y; aw[2] = a4_n.z; aw[3] = a4_n.w; }
        else        aw[0] = a1_n;
        if (i + 1 < end) {
            s_n = __ldg(&g_col[i + 1]);
            if (H == 4) a4_n = __ldg(&((const float4*)alpha)[i + 1]);
            else        a1_n = __ldg(&alpha[i + 1]);
        }
        const float* hrow = hfeat + (size_t)s * F;
        float v[PER];
#pragma unroll
        for (int p = 0; p < PER; p++) v[p] = __ldg(&hrow[lane + p * 32]);
#pragma unroll
        for (int p = 0; p < PER; p++) acc[p] += aw[H == 4 ? (p >> 1) : 0] * v[p];
        i++;
    }

    float* orow = out + (size_t)d * F;
#pragma unroll
    for (int p = 0; p < PER; p++) {
        int cidx = lane + p * 32;
        float v = acc[p] + __ldg(&bias[cidx]);
        orow[cidx] = v > 0.f ? v : (expf(v) - 1.f);   // ELU
    }
    // zero alpha accumulators for the next layer's fused-GEMM atomics
    if (lane < 4) { g_as[d * 4 + lane] = 0.f; g_ad[d * 4 + lane] = 0.f; }
}

// ---------------- final FC: [N,64] @ [64,5] + b ----------------
__global__ void k_fc(const float* __restrict__ in, const float* __restrict__ w,
                     const float* __restrict__ b, float* __restrict__ out) {
    int n = blockIdx.x * blockDim.x + threadIdx.x;
    if (n >= NN) return;
    const float4* hp = (const float4*)(in + (size_t)n * 64);
    float acc[5];
#pragma unroll
    for (int j = 0; j < 5; j++) acc[j] = __ldg(&b[j]);
#pragma unroll
    for (int k4 = 0; k4 < 16; k4++) {
        float4 v = hp[k4];
        float hv[4] = {v.x, v.y, v.z, v.w};
#pragma unroll
        for (int cc = 0; cc < 4; cc++) {
            int k = k4 * 4 + cc;
#pragma unroll
            for (int j = 0; j < 5; j++) acc[j] += hv[cc] * __ldg(&w[k * 5 + j]);
        }
    }
#pragma unroll
    for (int j = 0; j < 5; j++) out[(size_t)n * 5 + j] = acc[j];
}

// ---------------- launch ----------------
extern "C" void kernel_launch(void* const* d_in, const int* in_sizes, int n_in,
                              void* d_out, int out_size) {
    const int*   x   = (const int*)d_in[0];
    const int*   ei  = (const int*)d_in[1];
    const float* emb = (const float*)d_in[2];
    const float* W1  = (const float*)d_in[3];
    const float* a1s = (const float*)d_in[4];
    const float* a1d = (const float*)d_in[5];
    const float* b1  = (const float*)d_in[6];
    const float* W2  = (const float*)d_in[7];
    const float* a2s = (const float*)d_in[8];
    const float* a2d = (const float*)d_in[9];
    const float* b2  = (const float*)d_in[10];
    const float* W3  = (const float*)d_in[11];
    const float* a3s = (const float*)d_in[12];
    const float* a3d = (const float*)d_in[13];
    const float* b3  = (const float*)d_in[14];
    const float* fcw = (const float*)d_in[15];
    const float* fcb = (const float*)d_in[16];
    float* out = (float*)d_out;

    float *bufA, *bufB, *as_, *ad_, *alpha;
    cudaGetSymbolAddress((void**)&bufA, g_bufA);
    cudaGetSymbolAddress((void**)&bufB, g_bufB);
    cudaGetSymbolAddress((void**)&as_, g_as);
    cudaGetSymbolAddress((void**)&ad_, g_ad);
    cudaGetSymbolAddress((void**)&alpha, g_alpha);

    const int aggBlocks = (NN * 32) / 256;   // one warp per node

    // 0: embedding (+ zero cnt/as/ad)
    k_embed<<<(NN * 64) / 256, 256>>>(x, emb, bufA);
    // 1-2: CSR part 1
    k_hist<<<ET / 256, 256>>>(ei);
    k_chunk_sum<<<256, 256>>>();
    // 3: layer-1 GEMM (placed here so the fixed ncu capture lands on it)
    { dim3 g(2, NN / 128); k_gemm<128, 4><<<g, 256>>>(bufA, W1, bufB, a1s, a1d, as_, ad_, 64, 256); }
    // 4-5: CSR part 2
    k_rowptr2<<<256, 256>>>();
    k_scatter<<<ET / 256, 256>>>(ei);

    // ---- layer 1 attention + aggregation ----
    k_attn<4><<<aggBlocks, 256>>>(as_, ad_, alpha);
    k_agg2<4><<<aggBlocks, 256>>>(bufB, alpha, b1, bufA);

    // ---- layer 2 ----
    { dim3 g(2, NN / 128); k_gemm<128, 4><<<g, 256>>>(bufA, W2, bufB, a2s, a2d, as_, ad_, 256, 256); }
    k_attn<4><<<aggBlocks, 256>>>(as_, ad_, alpha);
    k_agg2<4><<<aggBlocks, 256>>>(bufB, alpha, b2, bufA);

    // ---- layer 3 ----
    { dim3 g(1, NN / 128); k_gemm<64, 1><<<g, 256>>>(bufA, W3, bufB, a3s, a3d, as_, ad_, 256, 64); }
    k_attn<1><<<aggBlocks, 256>>>(as_, ad_, alpha);
    k_agg2<1><<<aggBlocks, 256>>>(bufB, alpha, b3, bufA);

    // ---- FC head -> [N,5] ----
    k_fc<<<NN / 256, 256>>>(bufA, fcw, fcb, out);
}

// round 8
// speedup vs baseline: 1.1176x; 1.1005x over previous
#include <cuda_runtime.h>
#include <cstdint>
#include <math.h>

#define NN 131072
#define EE 1048576
#define ET (EE + NN)

// ---------------- scratch (device globals: no runtime allocation) ----------
__device__ float g_bufA[(size_t)NN * 256];   // 128 MB ping
__device__ float g_bufB[(size_t)NN * 256];   // 128 MB pong
__device__ float g_as[NN * 4];
__device__ float g_ad[NN * 4];
__device__ float g_alpha[(size_t)ET * 4];    // per-edge softmax weights
__device__ int   g_rowptr[NN + 1];
__device__ int   g_cnt[NN];
__device__ int   g_csum[256];
__device__ int   g_col[ET];

// packed dual-fp32 FMA: d = a*b + d (lane-wise on 2x f32)
__device__ __forceinline__ void ffma2(uint64_t& d, uint64_t a, uint64_t b) {
    asm("fma.rn.f32x2 %0, %1, %2, %0;" : "+l"(d) : "l"(a), "l"(b));
}
__device__ __forceinline__ uint64_t bcast2(float v) {
    uint64_t r;
    asm("mov.b64 %0, {%1, %1};" : "=l"(r) : "f"(v));
    return r;
}
union F4U { float4 f; uint64_t u[2]; };

// ---------------- embedding lookup (+ zero cnt & alpha accumulators) -------
__global__ void k_embed(const int* __restrict__ x, const float* __restrict__ emb,
                        float* __restrict__ out) {
    int i = blockIdx.x * blockDim.x + threadIdx.x;
    if (i < NN) g_cnt[i] = 0;
    if (i < NN * 4) { g_as[i] = 0.f; g_ad[i] = 0.f; }
    if (i < NN * 64) out[i] = __ldg(&emb[x[i >> 6] * 64 + (i & 63)]);
}

// ---------------- CSR build ----------------
__global__ void k_hist(const int* __restrict__ ei) {
    int e = blockIdx.x * blockDim.x + threadIdx.x;
    if (e >= ET) return;
    int dst = (e < EE) ? ei[EE + e] : (e - EE);
    atomicAdd(&g_cnt[dst], 1);
}
__global__ void k_chunk_sum() {
    __shared__ int sh[256];
    int b = blockIdx.x, t = threadIdx.x;
    sh[t] = g_cnt[b * 512 + t] + g_cnt[b * 512 + 256 + t];
    __syncthreads();
    for (int o = 128; o; o >>= 1) {
        if (t < o) sh[t] += sh[t + o];
        __syncthreads();
    }
    if (!t) g_csum[b] = sh[0];
}
__global__ void k_rowptr2() {
    __shared__ int csum[256];
    __shared__ int ch[512];
    int b = blockIdx.x, t = threadIdx.x;
    csum[t] = g_csum[t];
    ch[t]       = g_cnt[b * 512 + t];
    ch[t + 256] = g_cnt[b * 512 + 256 + t];
    __syncthreads();
    if (!t) {
        int run = 0;
        for (int i = 0; i < b; i++) run += csum[i];
        for (int i = 0; i < 512; i++) { int v = ch[i]; ch[i] = run; run += v; }
    }
    __syncthreads();
    g_rowptr[b * 512 + t]       = ch[t];
    g_rowptr[b * 512 + 256 + t] = ch[t + 256];
    g_cnt[b * 512 + t] = 0;
    g_cnt[b * 512 + 256 + t] = 0;
    if (b == 255 && !t) g_rowptr[NN] = ET;
}
__global__ void k_scatter(const int* __restrict__ ei) {
    int e = blockIdx.x * blockDim.x + threadIdx.x;
    if (e >= ET) return;
    int src, dst;
    if (e < EE) { src = ei[e]; dst = ei[EE + e]; }
    else        { src = dst = e - EE; }
    int pos = g_rowptr[dst] + atomicAdd(&g_cnt[dst], 1);
    g_col[pos] = src;
}

// ======== fp32 GEMM (f32x2), 2 CTAs/SM, fused attention-logit epilogue ======
// C[Nr,M] = A[Nr,K] @ B[K,M]; per CTA 128 x TN tile, 256 threads, BK=16.
// Single smem buffer; LDGs issued before the barrier to overlap the wait.
template <int TN, int H>
__global__ void __launch_bounds__(256, 2) k_gemm(
        const float* __restrict__ A, const float* __restrict__ B,
        float* __restrict__ C,
        const float* __restrict__ a_src, const float* __restrict__ a_dst,
        float* __restrict__ as_, float* __restrict__ ad_,
        int K, int M) {
    const int NI = TN / 16;           // cols per thread (8 or 4)
    const int NP = NI / 2;            // f32x2 pairs
    const int BIT = TN / 64;          // B float4 loads per thread
    const int GROUP = 64 / NI;        // lanes covering one head's 64 cols
    __shared__ float As[16][136];     // [k][row]
    __shared__ float Bs[16][TN];      // [k][col]

    int tid = threadIdx.x;
    int tx = tid & 15, ty = tid >> 4;
    int row0 = blockIdx.y * 128, col0 = blockIdx.x * TN;

    uint64_t acc[8][NP];
#pragma unroll
    for (int i = 0; i < 8; i++)
#pragma unroll
        for (int j = 0; j < NP; j++) acc[i][j] = 0ull;

    int a_row = tid >> 1, a_kq = (tid & 1) * 8;
    int b_k = tid / (TN / 4), b_c = (tid % (TN / 4)) * 4;
    const int BKSTEP = 256 / (TN / 4);   // k rows covered per B load iteration

    int CH = K / 16;
    for (int ch = 0; ch < CH; ch++) {
        int k0 = ch * 16;
        // issue gmem loads before the barrier (overlaps barrier wait)
        const float* Ap = A + (size_t)(row0 + a_row) * K + k0 + a_kq;
        float4 av0 = *(const float4*)Ap;
        float4 av1 = *(const float4*)(Ap + 4);
        float4 bv[BIT];
#pragma unroll
        for (int it = 0; it < BIT; it++)
            bv[it] = *(const float4*)(B + (size_t)(k0 + b_k + it * BKSTEP) * M + col0 + b_c);
        if (ch > 0) __syncthreads();   // previous compute done reading smem
        As[a_kq + 0][a_row] = av0.x; As[a_kq + 1][a_row] = av0.y;
        As[a_kq + 2][a_row] = av0.z; As[a_kq + 3][a_row] = av0.w;
        As[a_kq + 4][a_row] = av1.x; As[a_kq + 5][a_row] = av1.y;
        As[a_kq + 6][a_row] = av1.z; As[a_kq + 7][a_row] = av1.w;
#pragma unroll
        for (int it = 0; it < BIT; it++)
            *(float4*)&Bs[b_k + it * BKSTEP][b_c] = bv[it];
        __syncthreads();
#pragma unroll
        for (int k = 0; k < 16; k++) {
            float4 a0 = *(const float4*)&As[k][ty * 8];
            float4 a1 = *(const float4*)&As[k][ty * 8 + 4];
            uint64_t bp[NP];
            F4U b0;
            b0.f = *(const float4*)&Bs[k][tx * NI];
            bp[0] = b0.u[0]; bp[1] = b0.u[1];
            if (NP == 4) {
                F4U b1;
                b1.f = *(const float4*)&Bs[k][tx * NI + 4];
                bp[2] = b1.u[0]; bp[3] = b1.u[1];
            }
            float ar[8] = {a0.x, a0.y, a0.z, a0.w, a1.x, a1.y, a1.z, a1.w};
#pragma unroll
            for (int i = 0; i < 8; i++) {
                uint64_t ai = bcast2(ar[i]);
#pragma unroll
                for (int j = 0; j < NP; j++) ffma2(acc[i][j], ai, bp[j]);
            }
        }
    }

    // epilogue: store C + fused attention logits
    int head = col0 / 64 + (tx * NI) / 64;
    int cib  = (tx * NI) % 64;
    float avs[NI], avd[NI];
#pragma unroll
    for (int cc = 0; cc < NI; cc++) {
        avs[cc] = __ldg(&a_src[head * 64 + cib + cc]);
        avd[cc] = __ldg(&a_dst[head * 64 + cib + cc]);
    }
#pragma unroll
    for (int i = 0; i < 8; i++) {
        int row = row0 + ty * 8 + i;
        float* cp = C + (size_t)row * M + col0 + tx * NI;
        float s = 0.f, dv = 0.f;
#pragma unroll
        for (int j = 0; j < NP; j++) {
            float2 v = *(float2*)&acc[i][j];
            *(float2*)(cp + j * 2) = v;
            s  += v.x * avs[j * 2] + v.y * avs[j * 2 + 1];
            dv += v.x * avd[j * 2] + v.y * avd[j * 2 + 1];
        }
#pragma unroll
        for (int o = 1; o < GROUP; o <<= 1) {
            s  += __shfl_xor_sync(0xffffffffu, s, o);
            dv += __shfl_xor_sync(0xffffffffu, dv, o);
        }
        if ((tx & (GROUP - 1)) == 0) {
            atomicAdd(&as_[(size_t)row * H + head], s);
            atomicAdd(&ad_[(size_t)row * H + head], dv);
        }
    }
}

// ---------------- edge softmax weights (two-sweep, warp per dst) -----------
template <int H>
__global__ void k_attn(const float* __restrict__ as_, const float* __restrict__ ad_,
                       float* __restrict__ alpha) {
    int warp = (blockIdx.x * blockDim.x + threadIdx.x) >> 5;
    int lane = threadIdx.x & 31;
    if (warp >= NN) return;
    int d = warp;

    float adv[H];
    if (H == 4) {
        float4 t = __ldg(&((const float4*)ad_)[d]);
        adv[0] = t.x; adv[1] = t.y; adv[2] = t.z; adv[3] = t.w;
    } else {
        adv[0] = __ldg(&ad_[d]);
    }
    float m[H], s[H];
#pragma unroll
    for (int h = 0; h < H; h++) { m[h] = -1e30f; s[h] = 0.f; }

    int beg = g_rowptr[d], end = g_rowptr[d + 1];
    for (int i = beg + lane; i < end; i += 32) {
        int src = __ldg(&g_col[i]);
        float av[H];
        if (H == 4) {
            float4 t = __ldg(&((const float4*)as_)[src]);
            av[0] = t.x; av[1] = t.y; av[2] = t.z; av[3] = t.w;
        } else av[0] = __ldg(&as_[src]);
#pragma unroll
        for (int h = 0; h < H; h++) {
            float e = av[h] + adv[h];
            e = e > 0.f ? e : 0.2f * e;
            float nm = fmaxf(m[h], e);
            s[h] = s[h] * __expf(m[h] - nm) + __expf(e - nm);
            m[h] = nm;
        }
    }
#pragma unroll
    for (int o = 16; o; o >>= 1) {
#pragma unroll
        for (int h = 0; h < H; h++) {
            float mo = __shfl_xor_sync(0xffffffffu, m[h], o);
            float so = __shfl_xor_sync(0xffffffffu, s[h], o);
            float nm = fmaxf(m[h], mo);
            s[h] = s[h] * __expf(m[h] - nm) + so * __expf(mo - nm);
            m[h] = nm;
        }
    }
    float inv[H];
#pragma unroll
    for (int h = 0; h < H; h++) inv[h] = 1.f / (s[h] + 1e-16f);

    for (int i = beg + lane; i < end; i += 32) {
        int src = __ldg(&g_col[i]);
        float av[H];
        if (H == 4) {
            float4 t = __ldg(&((const float4*)as_)[src]);
            av[0] = t.x; av[1] = t.y; av[2] = t.z; av[3] = t.w;
        } else av[0] = __ldg(&as_[src]);
        float w[H];
#pragma unroll
        for (int h = 0; h < H; h++) {
            float e = av[h] + adv[h];
            e = e > 0.f ? e : 0.2f * e;
            w[h] = __expf(e - m[h]) * inv[h];
        }
        if (H == 4) {
            ((float4*)alpha)[i] = make_float4(w[0], w[1], w[2], w[3]);
        } else alpha[i] = w[0];
    }
}

// ---------------- gather aggregation (+ zero alpha accumulators) -----------
template <int H>
__global__ void k_agg2(const float* __restrict__ hfeat,
                       const float* __restrict__ alpha,
                       const float* __restrict__ bias,
                       float* __restrict__ out) {
    const int F = H * 64;
    const int PER = F / 32;
    int warp = (blockIdx.x * blockDim.x + threadIdx.x) >> 5;
    int lane = threadIdx.x & 31;
    if (warp >= NN) return;
    int d = warp;

    float acc[PER];
#pragma unroll
    for (int p = 0; p < PER; p++) acc[p] = 0.f;

    int beg = g_rowptr[d], end = g_rowptr[d + 1];
    int i = beg;
    int s_n = 0;
    float4 a4_n = make_float4(0.f, 0.f, 0.f, 0.f);
    float a1_n = 0.f;
    if (i < end) {
        s_n = __ldg(&g_col[i]);
        if (H == 4) a4_n = __ldg(&((const float4*)alpha)[i]);
        else        a1_n = __ldg(&alpha[i]);
    }
    while (i < end) {
        int s = s_n;
        float aw[H];
        if (H == 4) { aw[0] = a4_n.x; aw[1] = a4_n.y; aw[2] = a4_n.z; aw[3] = a4_n.w; }
        else        aw[0] = a1_n;
        if (i + 1 < end) {
            s_n = __ldg(&g_col[i + 1]);
            if (H == 4) a4_n = __ldg(&((const float4*)alpha)[i + 1]);
            else        a1_n = __ldg(&alpha[i + 1]);
        }
        const float* hrow = hfeat + (size_t)s * F;
        float v[PER];
#pragma unroll
        for (int p = 0; p < PER; p++) v[p] = __ldg(&hrow[lane + p * 32]);
#pragma unroll
        for (int p = 0; p < PER; p++) acc[p] += aw[H == 4 ? (p >> 1) : 0] * v[p];
        i++;
    }

    float* orow = out + (size_t)d * F;
#pragma unroll
    for (int p = 0; p < PER; p++) {
        int cidx = lane + p * 32;
        float v = acc[p] + __ldg(&bias[cidx]);
        orow[cidx] = v > 0.f ? v : (expf(v) - 1.f);   // ELU
    }
    // zero alpha accumulators for the next layer's fused-GEMM atomics
    if (lane < 4) { g_as[d * 4 + lane] = 0.f; g_ad[d * 4 + lane] = 0.f; }
}

// ---------------- final FC: [N,64] @ [64,5] + b ----------------
__global__ void k_fc(const float* __restrict__ in, const float* __restrict__ w,
                     const float* __restrict__ b, float* __restrict__ out) {
    int n = blockIdx.x * blockDim.x + threadIdx.x;
    if (n >= NN) return;
    const float4* hp = (const float4*)(in + (size_t)n * 64);
    float acc[5];
#pragma unroll
    for (int j = 0; j < 5; j++) acc[j] = __ldg(&b[j]);
#pragma unroll
    for (int k4 = 0; k4 < 16; k4++) {
        float4 v = hp[k4];
        float hv[4] = {v.x, v.y, v.z, v.w};
#pragma unroll
        for (int cc = 0; cc < 4; cc++) {
            int k = k4 * 4 + cc;
#pragma unroll
            for (int j = 0; j < 5; j++) acc[j] += hv[cc] * __ldg(&w[k * 5 + j]);
        }
    }
#pragma unroll
    for (int j = 0; j < 5; j++) out[(size_t)n * 5 + j] = acc[j];
}

// ---------------- launch ----------------
extern "C" void kernel_launch(void* const* d_in, const int* in_sizes, int n_in,
                              void* d_out, int out_size) {
    const int*   x   = (const int*)d_in[0];
    const int*   ei  = (const int*)d_in[1];
    const float* emb = (const float*)d_in[2];
    const float* W1  = (const float*)d_in[3];
    const float* a1s = (const float*)d_in[4];
    const float* a1d = (const float*)d_in[5];
    const float* b1  = (const float*)d_in[6];
    const float* W2  = (const float*)d_in[7];
    const float* a2s = (const float*)d_in[8];
    const float* a2d = (const float*)d_in[9];
    const float* b2  = (const float*)d_in[10];
    const float* W3  = (const float*)d_in[11];
    const float* a3s = (const float*)d_in[12];
    const float* a3d = (const float*)d_in[13];
    const float* b3  = (const float*)d_in[14];
    const float* fcw = (const float*)d_in[15];
    const float* fcb = (const float*)d_in[16];
    float* out = (float*)d_out;

    float *bufA, *bufB, *as_, *ad_, *alpha;
    cudaGetSymbolAddress((void**)&bufA, g_bufA);
    cudaGetSymbolAddress((void**)&bufB, g_bufB);
    cudaGetSymbolAddress((void**)&as_, g_as);
    cudaGetSymbolAddress((void**)&ad_, g_ad);
    cudaGetSymbolAddress((void**)&alpha, g_alpha);

    const int aggBlocks = (NN * 32) / 256;   // one warp per node

    // 0: embedding (+ zero cnt/as/ad)
    k_embed<<<(NN * 64) / 256, 256>>>(x, emb, bufA);
    // 1-2: CSR part 1
    k_hist<<<ET / 256, 256>>>(ei);
    k_chunk_sum<<<256, 256>>>();
    // 3: layer-1 GEMM (kept at this index so ncu captures it again)
    { dim3 g(2, NN / 128); k_gemm<128, 4><<<g, 256>>>(bufA, W1, bufB, a1s, a1d, as_, ad_, 64, 256); }
    // 4-5: CSR part 2
    k_rowptr2<<<256, 256>>>();
    k_scatter<<<ET / 256, 256>>>(ei);

    // ---- layer 1 attention + aggregation ----
    k_attn<4><<<aggBlocks, 256>>>(as_, ad_, alpha);
    k_agg2<4><<<aggBlocks, 256>>>(bufB, alpha, b1, bufA);

    // ---- layer 2 ----
    { dim3 g(2, NN / 128); k_gemm<128, 4><<<g, 256>>>(bufA, W2, bufB, a2s, a2d, as_, ad_, 256, 256); }
    k_attn<4><<<aggBlocks, 256>>>(as_, ad_, alpha);
    k_agg2<4><<<aggBlocks, 256>>>(bufB, alpha, b2, bufA);

    // ---- layer 3 ----
    { dim3 g(1, NN / 128); k_gemm<64, 1><<<g, 256>>>(bufA, W3, bufB, a3s, a3d, as_, ad_, 256, 64); }
    k_attn<1><<<aggBlocks, 256>>>(as_, ad_, alpha);
    k_agg2<1><<<aggBlocks, 256>>>(bufB, alpha, b3, bufA);

    // ---- FC head -> [N,5] ----
    k_fc<<<NN / 256, 256>>>(bufA, fcw, fcb, out);
}

// round 11
// speedup vs baseline: 1.1934x; 1.0678x over previous
#include <cuda_runtime.h>
#include <cstdint>
#include <math.h>

#define NN 131072
#define EE 1048576
#define ET (EE + NN)

// ---------------- scratch (device globals: no runtime allocation) ----------
__device__ float g_bufA[(size_t)NN * 256];   // 128 MB ping
__device__ float g_bufB[(size_t)NN * 256];   // 128 MB pong
__device__ float g_as[NN * 4];
__device__ float g_ad[NN * 4];
__device__ float g_alpha[(size_t)ET * 4];    // per-edge softmax weights
__device__ int   g_rowptr[NN + 1];
__device__ int   g_cnt[NN];
__device__ int   g_csum[256];
__device__ int   g_col[ET];

// packed dual-fp32 FMA: d = a*b + d (lane-wise on 2x f32)
__device__ __forceinline__ void ffma2(uint64_t& d, uint64_t a, uint64_t b) {
    asm("fma.rn.f32x2 %0, %1, %2, %0;" : "+l"(d) : "l"(a), "l"(b));
}
__device__ __forceinline__ uint64_t bcast2(float v) {
    uint64_t r;
    asm("mov.b64 %0, {%1, %1};" : "=l"(r) : "f"(v));
    return r;
}
union F4U { float4 f; uint64_t u[2]; };

// ---------------- embedding lookup (+ zero cnt & alpha accumulators) -------
__global__ void k_embed(const int* __restrict__ x, const float* __restrict__ emb,
                        float* __restrict__ out) {
    int i = blockIdx.x * blockDim.x + threadIdx.x;
    if (i < NN) g_cnt[i] = 0;
    if (i < NN * 4) { g_as[i] = 0.f; g_ad[i] = 0.f; }
    if (i < NN * 64) out[i] = __ldg(&emb[x[i >> 6] * 64 + (i & 63)]);
}

// ---------------- CSR build ----------------
__global__ void k_hist(const int* __restrict__ ei) {
    int e = blockIdx.x * blockDim.x + threadIdx.x;
    if (e >= ET) return;
    int dst = (e < EE) ? ei[EE + e] : (e - EE);
    atomicAdd(&g_cnt[dst], 1);
}
__global__ void k_chunk_sum() {
    __shared__ int sh[256];
    int b = blockIdx.x, t = threadIdx.x;
    sh[t] = g_cnt[b * 512 + t] + g_cnt[b * 512 + 256 + t];
    __syncthreads();
    for (int o = 128; o; o >>= 1) {
        if (t < o) sh[t] += sh[t + o];
        __syncthreads();
    }
    if (!t) g_csum[b] = sh[0];
}
__global__ void k_rowptr2() {
    __shared__ int csum[256];
    __shared__ int ch[512];
    int b = blockIdx.x, t = threadIdx.x;
    csum[t] = g_csum[t];
    ch[t]       = g_cnt[b * 512 + t];
    ch[t + 256] = g_cnt[b * 512 + 256 + t];
    __syncthreads();
    if (!t) {
        int run = 0;
        for (int i = 0; i < b; i++) run += csum[i];
        for (int i = 0; i < 512; i++) { int v = ch[i]; ch[i] = run; run += v; }
    }
    __syncthreads();
    g_rowptr[b * 512 + t]       = ch[t];
    g_rowptr[b * 512 + 256 + t] = ch[t + 256];
    g_cnt[b * 512 + t] = 0;
    g_cnt[b * 512 + 256 + t] = 0;
    if (b == 255 && !t) g_rowptr[NN] = ET;
}
__global__ void k_scatter(const int* __restrict__ ei) {
    int e = blockIdx.x * blockDim.x + threadIdx.x;
    if (e >= ET) return;
    int src, dst;
    if (e < EE) { src = ei[e]; dst = ei[EE + e]; }
    else        { src = dst = e - EE; }
    int pos = g_rowptr[dst] + atomicAdd(&g_cnt[dst], 1);
    g_col[pos] = src;
}

// ======== fp32 GEMM (f32x2), 2 CTAs/SM, fused attention-logit epilogue ======
// C[Nr,M] = A[Nr,K] @ B[K,M]; per CTA 128 x TN tile, 256 threads, BK=16.
// Thread cols: NG groups of 4, at g*64 + tx*4 -> contiguous 256B B-LDS per warp.
template <int TN, int H>
__global__ void __launch_bounds__(256, 2) k_gemm(
        const float* __restrict__ A, const float* __restrict__ B,
        float* __restrict__ C,
        const float* __restrict__ a_src, const float* __restrict__ a_dst,
        float* __restrict__ as_, float* __restrict__ ad_,
        int K, int M) {
    const int NG  = TN / 64;          // column groups per thread (2 or 1)
    const int BIT = TN / 64;          // B float4 loads per thread
    __shared__ float As[16][136];     // [k][row]
    __shared__ float Bs[16][TN];      // [k][col]

    int tid = threadIdx.x;
    int tx = tid & 15, ty = tid >> 4;
    int row0 = blockIdx.y * 128, col0 = blockIdx.x * TN;

    uint64_t acc[8][NG * 2];
#pragma unroll
    for (int i = 0; i < 8; i++)
#pragma unroll
        for (int j = 0; j < NG * 2; j++) acc[i][j] = 0ull;

    int a_row = tid >> 1, a_kq = (tid & 1) * 8;
    int b_k = tid / (TN / 4), b_c = (tid % (TN / 4)) * 4;
    const int BKSTEP = 256 / (TN / 4);   // k rows covered per B load iteration

    int CH = K / 16;
    for (int ch = 0; ch < CH; ch++) {
        int k0 = ch * 16;
        // issue gmem loads before the barrier (overlaps barrier wait)
        const float* Ap = A + (size_t)(row0 + a_row) * K + k0 + a_kq;
        float4 av0 = *(const float4*)Ap;
        float4 av1 = *(const float4*)(Ap + 4);
        float4 bv[BIT];
#pragma unroll
        for (int it = 0; it < BIT; it++)
            bv[it] = *(const float4*)(B + (size_t)(k0 + b_k + it * BKSTEP) * M + col0 + b_c);
        if (ch > 0) __syncthreads();   // previous compute done reading smem
        As[a_kq + 0][a_row] = av0.x; As[a_kq + 1][a_row] = av0.y;
        As[a_kq + 2][a_row] = av0.z; As[a_kq + 3][a_row] = av0.w;
        As[a_kq + 4][a_row] = av1.x; As[a_kq + 5][a_row] = av1.y;
        As[a_kq + 6][a_row] = av1.z; As[a_kq + 7][a_row] = av1.w;
#pragma unroll
        for (int it = 0; it < BIT; it++)
            *(float4*)&Bs[b_k + it * BKSTEP][b_c] = bv[it];
        __syncthreads();
#pragma unroll
        for (int k = 0; k < 16; k++) {
            float4 a0 = *(const float4*)&As[k][ty * 8];
            float4 a1 = *(const float4*)&As[k][ty * 8 + 4];
            uint64_t bp[NG * 2];
#pragma unroll
            for (int g = 0; g < NG; g++) {
                F4U bg;
                bg.f = *(const float4*)&Bs[k][g * 64 + tx * 4];
                bp[g * 2] = bg.u[0]; bp[g * 2 + 1] = bg.u[1];
            }
            float ar[8] = {a0.x, a0.y, a0.z, a0.w, a1.x, a1.y, a1.z, a1.w};
#pragma unroll
            for (int i = 0; i < 8; i++) {
                uint64_t ai = bcast2(ar[i]);
#pragma unroll
                for (int j = 0; j < NG * 2; j++) ffma2(acc[i][j], ai, bp[j]);
            }
        }
    }

    // epilogue: store C (STG.128, coalesced) + fused attention logits
    int h0 = col0 / 64;
    float avs[NG][4], avd[NG][4];
#pragma unroll
    for (int g = 0; g < NG; g++)
#pragma unroll
        for (int cc = 0; cc < 4; cc++) {
            avs[g][cc] = __ldg(&a_src[(h0 + g) * 64 + tx * 4 + cc]);
            avd[g][cc] = __ldg(&a_dst[(h0 + g) * 64 + tx * 4 + cc]);
        }
#pragma unroll
    for (int i = 0; i < 8; i++) {
        int row = row0 + ty * 8 + i;
        float s[NG], dv[NG];
#pragma unroll
        for (int g = 0; g < NG; g++) {
            float2 v0 = *(float2*)&acc[i][g * 2];
            float2 v1 = *(float2*)&acc[i][g * 2 + 1];
            *(float4*)(C + (size_t)row * M + col0 + g * 64 + tx * 4) =
                make_float4(v0.x, v0.y, v1.x, v1.y);
            s[g]  = v0.x * avs[g][0] + v0.y * avs[g][1] + v1.x * avs[g][2] + v1.y * avs[g][3];
            dv[g] = v0.x * avd[g][0] + v0.y * avd[g][1] + v1.x * avd[g][2] + v1.y * avd[g][3];
        }
#pragma unroll
        for (int o = 1; o < 16; o <<= 1)
#pragma unroll
            for (int g = 0; g < NG; g++) {
                s[g]  += __shfl_xor_sync(0xffffffffu, s[g], o);
                dv[g] += __shfl_xor_sync(0xffffffffu, dv[g], o);
            }
        if (tx == 0)
#pragma unroll
            for (int g = 0; g < NG; g++) {
                atomicAdd(&as_[(size_t)row * H + h0 + g], s[g]);
                atomicAdd(&ad_[(size_t)row * H + h0 + g], dv[g]);
            }
    }
}

// ---------------- edge softmax weights (two-sweep, warp per dst) -----------
template <int H>
__global__ void k_attn(const float* __restrict__ as_, const float* __restrict__ ad_,
                       float* __restrict__ alpha) {
    int warp = (blockIdx.x * blockDim.x + threadIdx.x) >> 5;
    int lane = threadIdx.x & 31;
    if (warp >= NN) return;
    int d = warp;

    float adv[H];
    if (H == 4) {
        float4 t = __ldg(&((const float4*)ad_)[d]);
        adv[0] = t.x; adv[1] = t.y; adv[2] = t.z; adv[3] = t.w;
    } else {
        adv[0] = __ldg(&ad_[d]);
    }
    float m[H], s[H];
#pragma unroll
    for (int h = 0; h < H; h++) { m[h] = -1e30f; s[h] = 0.f; }

    int beg = g_rowptr[d], end = g_rowptr[d + 1];
    for (int i = beg + lane; i < end; i += 32) {
        int src = __ldg(&g_col[i]);
        float av[H];
        if (H == 4) {
            float4 t = __ldg(&((const float4*)as_)[src]);
            av[0] = t.x; av[1] = t.y; av[2] = t.z; av[3] = t.w;
        } else av[0] = __ldg(&as_[src]);
#pragma unroll
        for (int h = 0; h < H; h++) {
            float e = av[h] + adv[h];
            e = e > 0.f ? e : 0.2f * e;
            float nm = fmaxf(m[h], e);
            s[h] = s[h] * __expf(m[h] - nm) + __expf(e - nm);
            m[h] = nm;
        }
    }
#pragma unroll
    for (int o = 16; o; o >>= 1) {
#pragma unroll
        for (int h = 0; h < H; h++) {
            float mo = __shfl_xor_sync(0xffffffffu, m[h], o);
            float so = __shfl_xor_sync(0xffffffffu, s[h], o);
            float nm = fmaxf(m[h], mo);
            s[h] = s[h] * __expf(m[h] - nm) + so * __expf(mo - nm);
            m[h] = nm;
        }
    }
    float inv[H];
#pragma unroll
    for (int h = 0; h < H; h++) inv[h] = 1.f / (s[h] + 1e-16f);

    for (int i = beg + lane; i < end; i += 32) {
        int src = __ldg(&g_col[i]);
        float av[H];
        if (H == 4) {
            float4 t = __ldg(&((const float4*)as_)[src]);
            av[0] = t.x; av[1] = t.y; av[2] = t.z; av[3] = t.w;
        } else av[0] = __ldg(&as_[src]);
        float w[H];
#pragma unroll
        for (int h = 0; h < H; h++) {
            float e = av[h] + adv[h];
            e = e > 0.f ? e : 0.2f * e;
            w[h] = __expf(e - m[h]) * inv[h];
        }
        if (H == 4) {
            ((float4*)alpha)[i] = make_float4(w[0], w[1], w[2], w[3]);
        } else alpha[i] = w[0];
    }
}

// ---------------- gather aggregation (+ zero alpha accumulators) -----------
template <int H>
__global__ void k_agg2(const float* __restrict__ hfeat,
                       const float* __restrict__ alpha,
                       const float* __restrict__ bias,
                       float* __restrict__ out) {
    const int F = H * 64;
    const int PER = F / 32;
    int warp = (blockIdx.x * blockDim.x + threadIdx.x) >> 5;
    int lane = threadIdx.x & 31;
    if (warp >= NN) return;
    int d = warp;

    float acc[PER];
#pragma unroll
    for (int p = 0; p < PER; p++) acc[p] = 0.f;

    int beg = g_rowptr[d], end = g_rowptr[d + 1];
    int i = beg;
    int s_n = 0;
    float4 a4_n = make_float4(0.f, 0.f, 0.f, 0.f);
    float a1_n = 0.f;
    if (i < end) {
        s_n = __ldg(&g_col[i]);
        if (H == 4) a4_n = __ldg(&((const float4*)alpha)[i]);
        else        a1_n = __ldg(&alpha[i]);
    }
    while (i < end) {
        int s = s_n;
        float aw[H];
        if (H == 4) { aw[0] = a4_n.x; aw[1] = a4_n.y; aw[2] = a4_n.z; aw[3] = a4_n.w; }
        else        aw[0] = a1_n;
        if (i + 1 < end) {
            s_n = __ldg(&g_col[i + 1]);
            if (H == 4) a4_n = __ldg(&((const float4*)alpha)[i + 1]);
            else        a1_n = __ldg(&alpha[i + 1]);
        }
        const float* hrow = hfeat + (size_t)s * F;
        float v[PER];
#pragma unroll
        for (int p = 0; p < PER; p++) v[p] = __ldg(&hrow[lane + p * 32]);
#pragma unroll
        for (int p = 0; p < PER; p++) acc[p] += aw[H == 4 ? (p >> 1) : 0] * v[p];
        i++;
    }

    float* orow = out + (size_t)d * F;
#pragma unroll
    for (int p = 0; p < PER; p++) {
        int cidx = lane + p * 32;
        float v = acc[p] + __ldg(&bias[cidx]);
        orow[cidx] = v > 0.f ? v : (expf(v) - 1.f);   // ELU
    }
    // zero alpha accumulators for the next layer's fused-GEMM atomics
    if (lane < 4) { g_as[d * 4 + lane] = 0.f; g_ad[d * 4 + lane] = 0.f; }
}

// ---------------- final FC: [N,64] @ [64,5] + b ----------------
__global__ void k_fc(const float* __restrict__ in, const float* __restrict__ w,
                     const float* __restrict__ b, float* __restrict__ out) {
    int n = blockIdx.x * blockDim.x + threadIdx.x;
    if (n >= NN) return;
    const float4* hp = (const float4*)(in + (size_t)n * 64);
    float acc[5];
#pragma unroll
    for (int j = 0; j < 5; j++) acc[j] = __ldg(&b[j]);
#pragma unroll
    for (int k4 = 0; k4 < 16; k4++) {
        float4 v = hp[k4];
        float hv[4] = {v.x, v.y, v.z, v.w};
#pragma unroll
        for (int cc = 0; cc < 4; cc++) {
            int k = k4 * 4 + cc;
#pragma unroll
            for (int j = 0; j < 5; j++) acc[j] += hv[cc] * __ldg(&w[k * 5 + j]);
        }
    }
#pragma unroll
    for (int j = 0; j < 5; j++) out[(size_t)n * 5 + j] = acc[j];
}

// ---------------- launch ----------------
extern "C" void kernel_launch(void* const* d_in, const int* in_sizes, int n_in,
                              void* d_out, int out_size) {
    const int*   x   = (const int*)d_in[0];
    const int*   ei  = (const int*)d_in[1];
    const float* emb = (const float*)d_in[2];
    const float* W1  = (const float*)d_in[3];
    const float* a1s = (const float*)d_in[4];
    const float* a1d = (const float*)d_in[5];
    const float* b1  = (const float*)d_in[6];
    const float* W2  = (const float*)d_in[7];
    const float* a2s = (const float*)d_in[8];
    const float* a2d = (const float*)d_in[9];
    const float* b2  = (const float*)d_in[10];
    const float* W3  = (const float*)d_in[11];
    const float* a3s = (const float*)d_in[12];
    const float* a3d = (const float*)d_in[13];
    const float* b3  = (const float*)d_in[14];
    const float* fcw = (const float*)d_in[15];
    const float* fcb = (const float*)d_in[16];
    float* out = (float*)d_out;

    float *bufA, *bufB, *as_, *ad_, *alpha;
    cudaGetSymbolAddress((void**)&bufA, g_bufA);
    cudaGetSymbolAddress((void**)&bufB, g_bufB);
    cudaGetSymbolAddress((void**)&as_, g_as);
    cudaGetSymbolAddress((void**)&ad_, g_ad);
    cudaGetSymbolAddress((void**)&alpha, g_alpha);

    const int aggBlocks = (NN * 32) / 256;   // one warp per node

    // 0: embedding (+ zero cnt/as/ad)
    k_embed<<<(NN * 64) / 256, 256>>>(x, emb, bufA);
    // 1-2: CSR part 1
    k_hist<<<ET / 256, 256>>>(ei);
    k_chunk_sum<<<256, 256>>>();
    // 3: layer-1 GEMM (kept at this index so ncu captures it again)
    { dim3 g(2, NN / 128); k_gemm<128, 4><<<g, 256>>>(bufA, W1, bufB, a1s, a1d, as_, ad_, 64, 256); }
    // 4-5: CSR part 2
    k_rowptr2<<<256, 256>>>();
    k_scatter<<<ET / 256, 256>>>(ei);

    // ---- layer 1 attention + aggregation ----
    k_attn<4><<<aggBlocks, 256>>>(as_, ad_, alpha);
    k_agg2<4><<<aggBlocks, 256>>>(bufB, alpha, b1, bufA);

    // ---- layer 2 ----
    { dim3 g(2, NN / 128); k_gemm<128, 4><<<g, 256>>>(bufA, W2, bufB, a2s, a2d, as_, ad_, 256, 256); }
    k_attn<4><<<aggBlocks, 256>>>(as_, ad_, alpha);
    k_agg2<4><<<aggBlocks, 256>>>(bufB, alpha, b2, bufA);

    // ---- layer 3 ----
    { dim3 g(1, NN / 128); k_gemm<64, 1><<<g, 256>>>(bufA, W3, bufB, a3s, a3d, as_, ad_, 256, 64); }
    k_attn<1><<<aggBlocks, 256>>>(as_, ad_, alpha);
    k_agg2<1><<<aggBlocks, 256>>>(bufB, alpha, b3, bufA);

    // ---- FC head -> [N,5] ----
    k_fc<<<NN / 256, 256>>>(bufA, fcw, fcb, out);
}